// round 12
// baseline (speedup 1.0000x reference)
#include <cuda_runtime.h>

#define Bb 16
#define Tt 160
#define Uu 80
#define U1 81
#define Vv 512
#define NDIAG 240     // diagonals d = t+u in [0,239]
#define DSTR 88       // diagonal row stride (floats), 16B aligned
#define L2E 1.4426950408889634f
#define LN2 0.6931471805599453f
#define NEG_INF __int_as_float(0xFF800000)
#define PADB Bb       // pad-fill blocks prepended to lse grid
#define XCH 40        // margin width = diagonals between warp refreshes

// Scratch (allocation-free rule). Tables: log2-domain, anti-diagonal layout.
__device__ float g_blank[Bb*NDIAG*DSTR];
__device__ float g_lab  [Bb*NDIAG*DSTR];
__device__ float g_ll   [Bb];
__device__ int   g_done;              // dp completion counter; self-resetting

// ---------------------------------------------------------------------------
__device__ __forceinline__ float exp_fast(float x) {   // FMA-only
    const float MAGIC = 12582912.0f;                    // 1.5 * 2^23
    float z = fmaf(x, L2E, MAGIC);
    float w = z - MAGIC;
    float f = fmaf(x, L2E, -w);
    float p =               9.6181291076e-3f;
    p = fmaf(p, f, 5.5504108664e-2f);
    p = fmaf(p, f, 2.4022650696e-1f);
    p = fmaf(p, f, 6.9314718056e-1f);
    p = fmaf(p, f, 1.0f);
    return __int_as_float(__float_as_int(p) + (__float_as_int(z) << 23));
}

// log2-domain logaddexp of (vs+bl, vl+la). Total function: output is always
// finite or -inf, never NaN (NaN from (-inf)-(-inf) clamped; fmaxf drops NaN).
__device__ __forceinline__ float dstep(float vs, float vl, float bl, float la) {
    float x = vs + bl;
    float y = vl + la;
    float mx = fmaxf(x, y);
    float nd = fmaxf(-fabsf(x - y), -126.0f);
    float e;  asm("ex2.approx.f32 %0, %1;" : "=f"(e) : "f"(nd));
    float l;  asm("lg2.approx.f32 %0, %1;" : "=f"(l) : "f"(1.0f + e));
    return mx + l;
}

__device__ __forceinline__ void cp16(unsigned int s, const void* g) {
    asm volatile("cp.async.cg.shared.global [%0], [%1], 16;" :: "r"(s), "l"(g));
}

// ---------------------------------------------------------------------------
// Kernel 1: blocks [0,PADB): geometry pad fill. Blocks >= PADB: per-row
// logsumexp over V=512 (dead rows write -inf and skip all logit traffic).
// ---------------------------------------------------------------------------
__global__ void __launch_bounds__(256) lse_kernel(const float* __restrict__ logits,
                                                  const int* __restrict__ targets,
                                                  const int* __restrict__ tl_arr,
                                                  const int* __restrict__ ul_arr) {
    if (blockIdx.x < PADB) {
        int b = blockIdx.x;
        float* bbl = g_blank + b * NDIAG * DSTR;
        float* bla = g_lab   + b * NDIAG * DSTR;
        for (int idx = threadIdx.x; idx < NDIAG * DSTR; idx += 256) {
            int d = idx / DSTR;
            int u = idx - d * DSTR;
            int lo = max(0, d - 159), hi = min(d, 80);
            if (u < lo || u > hi) { bbl[idx] = NEG_INF; bla[idx] = NEG_INF; }
        }
        return;
    }

    int gw   = ((blockIdx.x - PADB) * 256 + threadIdx.x) >> 5;  // row id
    int lane = threadIdx.x & 31;

    int u  = gw % U1;
    int bt = gw / U1;
    int t  = bt % Tt;
    int b  = bt / Tt;
    int o  = (b * NDIAG + (t + u)) * DSTR + u;
    if (t >= __ldg(tl_arr + b) || u > __ldg(ul_arr + b)) {  // dead row
        if (lane == 0) { g_blank[o] = NEG_INF; g_lab[o] = NEG_INF; }
        return;
    }

    const float4* p = reinterpret_cast<const float4*>(logits) + (size_t)gw * (Vv / 4);
    float4 a  = __ldcs(p + lane);
    float4 b4 = __ldcs(p + lane + 32);
    float4 c  = __ldcs(p + lane + 64);
    float4 dd = __ldcs(p + lane + 96);

    float s0 = (exp_fast(a.x)  + exp_fast(a.y))  + (exp_fast(a.z)  + exp_fast(a.w));
    float s1 = (exp_fast(b4.x) + exp_fast(b4.y)) + (exp_fast(b4.z) + exp_fast(b4.w));
    float s2 = (exp_fast(c.x)  + exp_fast(c.y))  + (exp_fast(c.z)  + exp_fast(c.w));
    float s3 = (exp_fast(dd.x) + exp_fast(dd.y)) + (exp_fast(dd.z) + exp_fast(dd.w));
    float s  = (s0 + s1) + (s2 + s3);
#pragma unroll
    for (int o2 = 16; o2; o2 >>= 1) s += __shfl_xor_sync(0xffffffffu, s, o2);

    float blank_logit = __shfl_sync(0xffffffffu, dd.w, 31);  // element 511

    if (lane == 0) {
        float lse2;
        asm("lg2.approx.f32 %0, %1;" : "=f"(lse2) : "f"(s));
        int tgt = targets[b * Uu + min(u, Uu - 1)];
        float lab_logit = __ldg(logits + (size_t)gw * Vv + tgt);
        g_blank[o] = fmaf(blank_logit, L2E, -lse2);
        g_lab[o]   = fmaf(lab_logit,   L2E, -lse2);
    }
}

// ---------------------------------------------------------------------------
// Kernel 2: MITM DP, one 128-thread block per batch; 4 warps:
//   w0: forward, owns cells 0..63 (self-contained; left deps only)
//   w1: forward, computes 24..87, authoritative 64..87; refreshed every XCH
//   w2: backward, computes 0..63, authoritative 0..23; refreshed every XCH
//   w3: backward, owns cells 24..87 (self-contained; right deps only)
// Combine at cut dm: log_like = LSE_u(alpha[dm][u] + beta[dm][u]).
// ---------------------------------------------------------------------------
__global__ void __launch_bounds__(128) dp_kernel(const int* __restrict__ tl_arr,
                                                 const int* __restrict__ ul_arr,
                                                 float* __restrict__ out) {
    extern __shared__ float sm[];
    float* s_bl  = sm;
    float* s_la  = sm + NDIAG * DSTR;
    float* s_x   = sm + 2 * NDIAG * DSTR;   // 40: fwd exchange (cells 24..63)
    float* s_y   = s_x + 40;                 // 40: bwd exchange (cells 24..63)
    float* s_alp = s_y + 40;                 // 88: alpha at the cut
    float* s_bet = s_alp + 88;               // 88: beta  at the cut
    int b = blockIdx.x;

    int tl = __ldg(tl_arr + b), ul = __ldg(ul_arr + b);
    int dtar = tl - 1 + ul;                  // in [119, 239] for this problem
    int dm   = dtar >> 1;

    // Async preload rows [0, dtar] of both tables (pads included).
    int n4 = (dtar + 1) * (DSTR / 4);
    const float4* gb = reinterpret_cast<const float4*>(g_blank + b * NDIAG * DSTR);
    const float4* gl = reinterpret_cast<const float4*>(g_lab   + b * NDIAG * DSTR);
    unsigned int sb = (unsigned int)__cvta_generic_to_shared(s_bl);
    unsigned int sl = (unsigned int)__cvta_generic_to_shared(s_la);
    for (int i = threadIdx.x; i < n4; i += 128) {
        cp16(sb + 16u * i, gb + i);
        cp16(sl + 16u * i, gl + i);
    }
    asm volatile("cp.async.commit_group;");
    asm volatile("cp.async.wait_group 0;");
    __syncthreads();

    int wid  = threadIdx.x >> 5;
    int lane = threadIdx.x & 31;
    int base = (wid & 1) ? 24 : 0;           // w0,w2: base 0; w1,w3: base 24
    int c0   = base + lane * 2;              // this lane's low cell

    if (wid < 2) {
        // =================== FORWARD alpha: diag 1 .. dm ====================
        float v0 = NEG_INF, v1 = NEG_INF;
        if (wid == 0 && lane == 0) v0 = 0.0f;       // alpha[0][0]
        float2 cbl = *reinterpret_cast<const float2*>(s_bl + c0);  // row 0
        float2 cla = *reinterpret_cast<const float2*>(s_la + c0);
        int cd = XCH;
        for (int d = 1; d <= dm; ++d) {
            float2 nbl = *reinterpret_cast<const float2*>(s_bl + d * DSTR + c0);
            float2 nla = *reinterpret_cast<const float2*>(s_la + d * DSTR + c0);
            float vleft = __shfl_up_sync(0xffffffffu, v1, 1);
            float lleft = __shfl_up_sync(0xffffffffu, cla.y, 1);
            if (wid == 0 && lane == 0) vleft = NEG_INF;  // cell 0: no left
            // (w1 lane 0: garbage vleft lands in margin cell 24 — by design)
            float nv0 = dstep(v0, vleft, cbl.x, lleft);
            float nv1 = dstep(v1, v0,    cbl.y, cla.x);
            v0 = nv0; v1 = nv1; cbl = nbl; cla = nla;
            if (--cd == 0) {                  // refresh w1's margin from w0
                cd = XCH;
                if (wid == 0 && lane >= 12) {        // cells 24..63
                    s_x[(lane - 12) * 2]     = v0;
                    s_x[(lane - 12) * 2 + 1] = v1;
                }
                asm volatile("bar.sync 2, 64;" ::: "memory");
                if (wid == 1 && lane < 20) {         // cells 24..63
                    v0 = s_x[lane * 2];
                    v1 = s_x[lane * 2 + 1];
                }
                asm volatile("bar.sync 2, 64;" ::: "memory");
            }
        }
        if (wid == 0)            { s_alp[c0] = v0; s_alp[c0 + 1] = v1; }  // 0..63
        else if (lane >= 20)     { s_alp[c0] = v0; s_alp[c0 + 1] = v1; }  // 64..87
    } else {
        // =================== BACKWARD beta: diag dtar-1 .. dm ===============
        float corner = s_bl[dtar * DSTR + ul];       // beta[tl-1][ul]
        float w0 = (c0     == ul) ? corner : NEG_INF;
        float w1 = (c0 + 1 == ul) ? corner : NEG_INF;
        float wr = __shfl_down_sync(0xffffffffu, w0, 1);   // cell c0+2, cur diag
        float2 cbl = *reinterpret_cast<const float2*>(s_bl + max(dtar - 1, 0) * DSTR + c0);
        float2 cla = *reinterpret_cast<const float2*>(s_la + max(dtar - 1, 0) * DSTR + c0);
        int cd = XCH;
        for (int d = dtar - 1; d >= dm; --d) {
            int dn = max(d - 1, 0);
            float2 nbl = *reinterpret_cast<const float2*>(s_bl + dn * DSTR + c0);
            float2 nla = *reinterpret_cast<const float2*>(s_la + dn * DSTR + c0);
            float nb0 = dstep(w0, w1, cbl.x, cla.x);
            float nwr = __shfl_down_sync(0xffffffffu, nb0, 1);
            float nb1 = dstep(w1, wr, cbl.y, cla.y);
            // (w3 lane 31: cell 87's right input masked by la[d][87] = -inf pad)
            w0 = nb0; w1 = nb1; wr = nwr; cbl = nbl; cla = nla;
            if (--cd == 0) {                  // refresh w2's margin from w3
                cd = XCH;
                if (wid == 3 && lane < 20) {         // cells 24..63
                    s_y[lane * 2]     = w0;
                    s_y[lane * 2 + 1] = w1;
                }
                asm volatile("bar.sync 3, 64;" ::: "memory");
                if (wid == 2 && lane >= 12) {        // cells 24..63
                    w0 = s_y[(lane - 12) * 2];
                    w1 = s_y[(lane - 12) * 2 + 1];
                }
                asm volatile("bar.sync 3, 64;" ::: "memory");
                wr = __shfl_down_sync(0xffffffffu, w0, 1);  // re-derive neighbor
            }
        }
        if (wid == 3)            { s_bet[c0] = w0; s_bet[c0 + 1] = w1; }  // 24..87
        else if (lane < 12)      { s_bet[c0] = w0; s_bet[c0 + 1] = w1; }  // 0..23
    }

    __syncthreads();
    if (wid != 0) return;

    // ---------------- Combine at the cut: LSE over valid u -------------------
    int lo = max(0, dm - (tl - 1));
    int hi = min(dm, ul);
    float t0 = NEG_INF, t1 = NEG_INF, t2 = NEG_INF;
    {
        int u = lane;
        if (u >= lo && u <= hi) t0 = s_alp[u] + s_bet[u];
        u = lane + 32;
        if (u >= lo && u <= hi) t1 = s_alp[u] + s_bet[u];
        u = lane + 64;
        if (u < 88 && u >= lo && u <= hi) t2 = s_alp[u] + s_bet[u];
    }
    float m = fmaxf(t0, fmaxf(t1, t2));
#pragma unroll
    for (int o = 16; o; o >>= 1) m = fmaxf(m, __shfl_xor_sync(0xffffffffu, m, o));

    float e0, e1, e2;
    float d0 = fmaxf(t0 - m, -126.0f);
    float d1 = fmaxf(t1 - m, -126.0f);
    float d2 = fmaxf(t2 - m, -126.0f);
    asm("ex2.approx.f32 %0, %1;" : "=f"(e0) : "f"(d0));
    asm("ex2.approx.f32 %0, %1;" : "=f"(e1) : "f"(d1));
    asm("ex2.approx.f32 %0, %1;" : "=f"(e2) : "f"(d2));
    float s = e0 + e1 + e2;
#pragma unroll
    for (int o = 16; o; o >>= 1) s += __shfl_xor_sync(0xffffffffu, s, o);

    if (lane == 0) {
        float l;  asm("lg2.approx.f32 %0, %1;" : "=f"(l) : "f"(s));
        g_ll[b] = m + l;                          // log2-domain log-likelihood
        __threadfence();
        int prev = atomicAdd(&g_done, 1);
        if (prev == Bb - 1) {                     // deterministic final reduce
            __threadfence();
            float sll = 0.0f;
#pragma unroll
            for (int i = 0; i < Bb; ++i) sll += __ldcg(&g_ll[i]);
            out[0] = sll * (-LN2 / (float)Bb);
            g_done = 0;                           // reset for next graph replay
        }
    }
}

extern "C" void kernel_launch(void* const* d_in, const int* in_sizes, int n_in,
                              void* d_out, int out_size) {
    const float* logits  = (const float*)d_in[0];
    const int*   targets = (const int*)d_in[1];
    const int*   tl      = (const int*)d_in[2];
    const int*   ul      = (const int*)d_in[3];

    const int ROWS = Bb * Tt * U1;                 // 207360 rows, 8 warps/block
    lse_kernel<<<PADB + ROWS / 8, 256>>>(logits, targets, tl, ul);

    size_t smem = (2 * NDIAG * DSTR + 256) * sizeof(float);  // tables + buffers
    cudaFuncSetAttribute(dp_kernel, cudaFuncAttributeMaxDynamicSharedMemorySize, (int)smem);
    dp_kernel<<<Bb, 128, smem>>>(tl, ul, (float*)d_out);
}

// round 13
// speedup vs baseline: 1.0731x; 1.0731x over previous
#include <cuda_runtime.h>

#define Bb 16
#define Tt 160
#define Uu 80
#define U1 81
#define Vv 512
#define NDIAG 240     // diagonals d = t+u in [0,239]
#define DSTR 88       // diagonal row stride (floats), 16B aligned
#define L2E 1.4426950408889634f
#define LN2 0.6931471805599453f
#define PADB Bb       // pad-fill blocks prepended to lse grid
#define RNORM 12      // diagonals between renormalizations
#define SC 9          // tables pre-scaled by 2^SC (2^9 = 512)

// Scratch (allocation-free rule). Tables: LINEAR probabilities * 2^SC,
// anti-diagonal layout. Dead rows / geometry pads hold exact 0.0f.
__device__ float g_blank[Bb*NDIAG*DSTR];
__device__ float g_lab  [Bb*NDIAG*DSTR];
__device__ float g_ll   [Bb];
__device__ int   g_done;              // dp completion counter; self-resetting

// ---------------------------------------------------------------------------
__device__ __forceinline__ float exp_fast(float x) {   // FMA-only e^x
    const float MAGIC = 12582912.0f;                    // 1.5 * 2^23
    float z = fmaf(x, L2E, MAGIC);
    float w = z - MAGIC;
    float f = fmaf(x, L2E, -w);
    float p =               9.6181291076e-3f;
    p = fmaf(p, f, 5.5504108664e-2f);
    p = fmaf(p, f, 2.4022650696e-1f);
    p = fmaf(p, f, 6.9314718056e-1f);
    p = fmaf(p, f, 1.0f);
    return __int_as_float(__float_as_int(p) + (__float_as_int(z) << 23));
}

__device__ __forceinline__ void cp16(unsigned int s, const void* g) {
    asm volatile("cp.async.cg.shared.global [%0], [%1], 16;" :: "r"(s), "l"(g));
}

__device__ __forceinline__ float warp_max(float x) {
#pragma unroll
    for (int o = 16; o; o >>= 1) x = fmaxf(x, __shfl_xor_sync(0xffffffffu, x, o));
    return x;
}
__device__ __forceinline__ float warp_sum(float x) {
#pragma unroll
    for (int o = 16; o; o >>= 1) x += __shfl_xor_sync(0xffffffffu, x, o);
    return x;
}

// ---------------------------------------------------------------------------
// Kernel 1: blocks [0,PADB): pad fill (0.0f). Blocks >= PADB: per-row softmax
// denominator; emits LINEAR probs * 2^SC (dead rows write 0 and skip traffic).
// ---------------------------------------------------------------------------
__global__ void __launch_bounds__(256) lse_kernel(const float* __restrict__ logits,
                                                  const int* __restrict__ targets,
                                                  const int* __restrict__ tl_arr,
                                                  const int* __restrict__ ul_arr) {
    if (blockIdx.x < PADB) {
        int b = blockIdx.x;
        float* bbl = g_blank + b * NDIAG * DSTR;
        float* bla = g_lab   + b * NDIAG * DSTR;
        for (int idx = threadIdx.x; idx < NDIAG * DSTR; idx += 256) {
            int d = idx / DSTR;
            int u = idx - d * DSTR;
            int lo = max(0, d - 159), hi = min(d, 80);
            if (u < lo || u > hi) { bbl[idx] = 0.0f; bla[idx] = 0.0f; }
        }
        return;
    }

    int gw   = ((blockIdx.x - PADB) * 256 + threadIdx.x) >> 5;  // row id
    int lane = threadIdx.x & 31;

    int u  = gw % U1;
    int bt = gw / U1;
    int t  = bt % Tt;
    int b  = bt / Tt;
    int o  = (b * NDIAG + (t + u)) * DSTR + u;
    if (t >= __ldg(tl_arr + b) || u > __ldg(ul_arr + b)) {  // dead row -> 0
        if (lane == 0) { g_blank[o] = 0.0f; g_lab[o] = 0.0f; }
        return;
    }

    const float4* p = reinterpret_cast<const float4*>(logits) + (size_t)gw * (Vv / 4);
    float4 a  = __ldcs(p + lane);
    float4 b4 = __ldcs(p + lane + 32);
    float4 c  = __ldcs(p + lane + 64);
    float4 dd = __ldcs(p + lane + 96);

    float s0 = (exp_fast(a.x)  + exp_fast(a.y))  + (exp_fast(a.z)  + exp_fast(a.w));
    float s1 = (exp_fast(b4.x) + exp_fast(b4.y)) + (exp_fast(b4.z) + exp_fast(b4.w));
    float s2 = (exp_fast(c.x)  + exp_fast(c.y))  + (exp_fast(c.z)  + exp_fast(c.w));
    float s3 = (exp_fast(dd.x) + exp_fast(dd.y)) + (exp_fast(dd.z) + exp_fast(dd.w));
    float s  = (s0 + s1) + (s2 + s3);
#pragma unroll
    for (int o2 = 16; o2; o2 >>= 1) s += __shfl_xor_sync(0xffffffffu, s, o2);

    float blank_logit = __shfl_sync(0xffffffffu, dd.w, 31);  // element 511

    if (lane == 0) {
        float rs = __fdividef(512.0f, s);     // 2^SC / sum  (MUFU rcp path)
        int tgt = targets[b * Uu + min(u, Uu - 1)];
        float lab_logit = __ldg(logits + (size_t)gw * Vv + tgt);
        g_blank[o] = exp_fast(blank_logit) * rs;   // pb * 2^SC
        g_lab[o]   = exp_fast(lab_logit)   * rs;   // pl * 2^SC
    }
}

// ---------------------------------------------------------------------------
// Kernel 2: MITM DP in LINEAR domain, one 64-thread block per batch.
//   warp0: forward alpha to cut dm (1 MUL + 1 FMA per cell per diagonal)
//   warp1: backward beta to dm
// Renorm every RNORM diagonals: warp-max -> scale by 2^(127-e), accumulate k.
// Combine: ll = lg2(sum_u A'[u]B'[u]) - SC*(dtar+1) + KF + KB   (log2 domain).
// ---------------------------------------------------------------------------
__global__ void __launch_bounds__(64) dp_kernel(const int* __restrict__ tl_arr,
                                                const int* __restrict__ ul_arr,
                                                float* __restrict__ out) {
    extern __shared__ float sm[];
    float* s_bl  = sm;
    float* s_la  = sm + NDIAG * DSTR;
    float* s_alp = sm + 2 * NDIAG * DSTR;        // 88: alpha' at the cut
    float* s_bet = s_alp + 88;                   // 88: beta'  at the cut
    int*   s_ki  = reinterpret_cast<int*>(s_bet + 88);  // [KF, KB]
    int b = blockIdx.x;

    int tl = __ldg(tl_arr + b), ul = __ldg(ul_arr + b);
    int dtar = tl - 1 + ul;
    int dm   = dtar >> 1;

    // Async preload rows [0, dtar] of both tables (pads included).
    int n4 = (dtar + 1) * (DSTR / 4);
    const float4* gb = reinterpret_cast<const float4*>(g_blank + b * NDIAG * DSTR);
    const float4* gl = reinterpret_cast<const float4*>(g_lab   + b * NDIAG * DSTR);
    unsigned int sb = (unsigned int)__cvta_generic_to_shared(s_bl);
    unsigned int sl = (unsigned int)__cvta_generic_to_shared(s_la);
    for (int i = threadIdx.x; i < n4; i += 64) {
        cp16(sb + 16u * i, gb + i);
        cp16(sl + 16u * i, gl + i);
    }
    asm volatile("cp.async.commit_group;");
    asm volatile("cp.async.wait_group 0;");
    __syncthreads();

    int wid  = threadIdx.x >> 5;
    int lane = threadIdx.x & 31;
    int u0   = lane * 4;
    int uoff = min(u0, 84);
    // renorm mask: cells beyond ul excluded from the max (values >= 0 always)
    bool m0 = (u0     <= ul), m1 = (u0 + 1 <= ul),
         m2 = (u0 + 2 <= ul), m3 = (u0 + 3 <= ul);

    if (wid == 0) {
        // =================== FORWARD alpha': diag 1 .. dm ====================
        float v0 = (lane == 0) ? 1.0f : 0.0f, v1 = 0.0f, v2 = 0.0f, v3 = 0.0f;
        int K = 0, cd = RNORM;
        float4 cbl = *reinterpret_cast<const float4*>(s_bl + uoff);  // row 0
        float4 cla = *reinterpret_cast<const float4*>(s_la + uoff);
        for (int d = 1; d <= dm; ++d) {
            float4 nbl = *reinterpret_cast<const float4*>(s_bl + d * DSTR + uoff);
            float4 nla = *reinterpret_cast<const float4*>(s_la + d * DSTR + uoff);
            float vleft = __shfl_up_sync(0xffffffffu, v3,    1);
            float lleft = __shfl_up_sync(0xffffffffu, cla.w, 1);
            if (lane == 0) vleft = 0.0f;         // cell 0 has no left neighbor
            float nv0 = fmaf(v0, cbl.x, vleft * lleft);
            float nv1 = fmaf(v1, cbl.y, v0 * cla.x);
            float nv2 = fmaf(v2, cbl.z, v1 * cla.y);
            float nv3 = fmaf(v3, cbl.w, v2 * cla.z);
            v0 = nv0; v1 = nv1; v2 = nv2; v3 = nv3;
            cbl = nbl; cla = nla;
            if (--cd == 0) {                     // renormalize
                cd = RNORM;
                float mx = fmaxf(fmaxf(m0 ? v0 : 0.0f, m1 ? v1 : 0.0f),
                                 fmaxf(m2 ? v2 : 0.0f, m3 ? v3 : 0.0f));
                mx = warp_max(mx);
                int e = (__float_as_int(mx) >> 23) & 0xFF;
                e = max(e, 1);
                float sc = __int_as_float((254 - e) << 23);  // 2^(127-e)
                v0 *= sc; v1 *= sc; v2 *= sc; v3 *= sc;
                K += e - 127;
            }
        }
        {   // final renorm (bound values before the cross-warp product)
            float mx = fmaxf(fmaxf(m0 ? v0 : 0.0f, m1 ? v1 : 0.0f),
                             fmaxf(m2 ? v2 : 0.0f, m3 ? v3 : 0.0f));
            mx = warp_max(mx);
            int e = (__float_as_int(mx) >> 23) & 0xFF;
            e = max(e, 1);
            float sc = __int_as_float((254 - e) << 23);
            v0 *= sc; v1 *= sc; v2 *= sc; v3 *= sc;
            K += e - 127;
        }
        *reinterpret_cast<float4*>(s_alp + uoff) = make_float4(v0, v1, v2, v3);
        if (lane == 0) s_ki[0] = K;
    } else {
        // =================== BACKWARD beta': diag dtar-1 .. dm ===============
        float corner = s_bl[dtar * DSTR + ul];   // beta[tl-1][ul] = pb' there
        float w0 = (u0     == ul) ? corner : 0.0f;
        float w1 = (u0 + 1 == ul) ? corner : 0.0f;
        float w2 = (u0 + 2 == ul) ? corner : 0.0f;
        float w3 = (u0 + 3 == ul) ? corner : 0.0f;
        float wr = __shfl_down_sync(0xffffffffu, w0, 1);   // cell u0+4, cur diag
        int K = 0, cd = RNORM;
        float4 cbl, cla;
        if (dtar > dm) {
            cbl = *reinterpret_cast<const float4*>(s_bl + (dtar - 1) * DSTR + uoff);
            cla = *reinterpret_cast<const float4*>(s_la + (dtar - 1) * DSTR + uoff);
        }
        for (int d = dtar - 1; d >= dm; --d) {
            int dn = max(d - 1, 0);
            float4 nbl = *reinterpret_cast<const float4*>(s_bl + dn * DSTR + uoff);
            float4 nla = *reinterpret_cast<const float4*>(s_la + dn * DSTR + uoff);
            float nb0 = fmaf(w0, cbl.x, w1 * cla.x);
            float nwr = __shfl_down_sync(0xffffffffu, nb0, 1);
            float nb1 = fmaf(w1, cbl.y, w2 * cla.y);
            float nb2 = fmaf(w2, cbl.z, w3 * cla.z);
            float nb3 = fmaf(w3, cbl.w, wr * cla.w);  // cell 87: cla.w = 0 pad
            w0 = nb0; w1 = nb1; w2 = nb2; w3 = nb3; wr = nwr;
            cbl = nbl; cla = nla;
            if (--cd == 0) {                     // renormalize (all cells valid-or-0)
                cd = RNORM;
                float mx = warp_max(fmaxf(fmaxf(w0, w1), fmaxf(w2, w3)));
                int e = (__float_as_int(mx) >> 23) & 0xFF;
                e = max(e, 1);
                float sc = __int_as_float((254 - e) << 23);
                w0 *= sc; w1 *= sc; w2 *= sc; w3 *= sc;
                wr *= sc;                        // neighbor carries same scale
                K += e - 127;
            }
        }
        {   // final renorm
            float mx = warp_max(fmaxf(fmaxf(w0, w1), fmaxf(w2, w3)));
            int e = (__float_as_int(mx) >> 23) & 0xFF;
            e = max(e, 1);
            float sc = __int_as_float((254 - e) << 23);
            w0 *= sc; w1 *= sc; w2 *= sc; w3 *= sc;
            K += e - 127;
        }
        *reinterpret_cast<float4*>(s_bet + uoff) = make_float4(w0, w1, w2, w3);
        if (lane == 0) s_ki[1] = K;
    }

    __syncthreads();
    if (wid != 0) return;

    // ---------------- Combine at the cut: masked dot product ----------------
    int lo = max(0, dm - (tl - 1));
    int hi = min(dm, ul);
    float S = 0.0f;
    {
        int u = lane;
        if (u >= lo && u <= hi) S += s_alp[u] * s_bet[u];
        u = lane + 32;
        if (u >= lo && u <= hi) S += s_alp[u] * s_bet[u];
        u = lane + 64;
        if (u < 88 && u >= lo && u <= hi) S += s_alp[u] * s_bet[u];
    }
    S = warp_sum(S);

    if (lane == 0) {
        float l;  asm("lg2.approx.f32 %0, %1;" : "=f"(l) : "f"(S));
        // A' = alpha*2^(SC*dm-KF); B' = beta*2^(SC*(dtar-dm+1)-KB)
        g_ll[b] = l - (float)(SC * (dtar + 1)) + (float)(s_ki[0] + s_ki[1]);
        __threadfence();
        int prev = atomicAdd(&g_done, 1);
        if (prev == Bb - 1) {                     // deterministic final reduce
            __threadfence();
            float sll = 0.0f;
#pragma unroll
            for (int i = 0; i < Bb; ++i) sll += __ldcg(&g_ll[i]);
            out[0] = sll * (-LN2 / (float)Bb);
            g_done = 0;                           // reset for next graph replay
        }
    }
}

extern "C" void kernel_launch(void* const* d_in, const int* in_sizes, int n_in,
                              void* d_out, int out_size) {
    const float* logits  = (const float*)d_in[0];
    const int*   targets = (const int*)d_in[1];
    const int*   tl      = (const int*)d_in[2];
    const int*   ul      = (const int*)d_in[3];

    const int ROWS = Bb * Tt * U1;                 // 207360 rows, 8 warps/block
    lse_kernel<<<PADB + ROWS / 8, 256>>>(logits, targets, tl, ul);

    size_t smem = (2 * NDIAG * DSTR + 256) * sizeof(float);  // tables + buffers
    cudaFuncSetAttribute(dp_kernel, cudaFuncAttributeMaxDynamicSharedMemorySize, (int)smem);
    dp_kernel<<<Bb, 64, smem>>>(tl, ul, (float*)d_out);
}

// round 14
// speedup vs baseline: 1.0774x; 1.0040x over previous
#include <cuda_runtime.h>

#define Bb 16
#define Tt 160
#define Uu 80
#define U1 81
#define Vv 512
#define NDIAG 240     // diagonals d = t+u in [0,239]
#define DSTR 88       // diagonal row stride (floats), 16B aligned
#define L2E 1.4426950408889634f
#define LN2 0.6931471805599453f
#define PADB Bb       // pad-fill blocks prepended to lse grid
#define RNORM 12      // diagonals between renormalizations
#define SC 9          // tables pre-scaled by 2^SC (2^9 = 512)

// Scratch (allocation-free rule). Tables: LINEAR probabilities * 2^SC,
// anti-diagonal layout. Dead rows / geometry pads hold exact 0.0f.
__device__ float g_blank[Bb*NDIAG*DSTR];
__device__ float g_lab  [Bb*NDIAG*DSTR];
__device__ float g_ll   [Bb];
__device__ int   g_done;              // dp completion counter; self-resetting

// ---------------------------------------------------------------------------
__device__ __forceinline__ float exp_fast(float x) {   // FMA-only e^x
    const float MAGIC = 12582912.0f;                    // 1.5 * 2^23
    float z = fmaf(x, L2E, MAGIC);
    float w = z - MAGIC;
    float f = fmaf(x, L2E, -w);
    float p =               9.6181291076e-3f;
    p = fmaf(p, f, 5.5504108664e-2f);
    p = fmaf(p, f, 2.4022650696e-1f);
    p = fmaf(p, f, 6.9314718056e-1f);
    p = fmaf(p, f, 1.0f);
    return __int_as_float(__float_as_int(p) + (__float_as_int(z) << 23));
}

__device__ __forceinline__ void cp16(unsigned int s, const void* g) {
    asm volatile("cp.async.cg.shared.global [%0], [%1], 16;" :: "r"(s), "l"(g));
}

__device__ __forceinline__ float warp_max(float x) {
#pragma unroll
    for (int o = 16; o; o >>= 1) x = fmaxf(x, __shfl_xor_sync(0xffffffffu, x, o));
    return x;
}
__device__ __forceinline__ float warp_sum(float x) {
#pragma unroll
    for (int o = 16; o; o >>= 1) x += __shfl_xor_sync(0xffffffffu, x, o);
    return x;
}

// ---------------------------------------------------------------------------
// Kernel 1: blocks [0,PADB): pad fill (0.0f). Blocks >= PADB: per-row softmax
// denominator; emits LINEAR probs * 2^SC (dead rows write 0 and skip traffic).
// Every block triggers programmatic launch completion immediately so the dp
// kernel's blocks come resident and wait on the HW grid dependency.
// ---------------------------------------------------------------------------
__global__ void __launch_bounds__(256) lse_kernel(const float* __restrict__ logits,
                                                  const int* __restrict__ targets,
                                                  const int* __restrict__ tl_arr,
                                                  const int* __restrict__ ul_arr) {
    cudaTriggerProgrammaticLaunchCompletion();

    if (blockIdx.x < PADB) {
        int b = blockIdx.x;
        float* bbl = g_blank + b * NDIAG * DSTR;
        float* bla = g_lab   + b * NDIAG * DSTR;
        for (int idx = threadIdx.x; idx < NDIAG * DSTR; idx += 256) {
            int d = idx / DSTR;
            int u = idx - d * DSTR;
            int lo = max(0, d - 159), hi = min(d, 80);
            if (u < lo || u > hi) { bbl[idx] = 0.0f; bla[idx] = 0.0f; }
        }
        return;
    }

    int gw   = ((blockIdx.x - PADB) * 256 + threadIdx.x) >> 5;  // row id
    int lane = threadIdx.x & 31;

    int u  = gw % U1;
    int bt = gw / U1;
    int t  = bt % Tt;
    int b  = bt / Tt;
    int o  = (b * NDIAG + (t + u)) * DSTR + u;
    if (t >= __ldg(tl_arr + b) || u > __ldg(ul_arr + b)) {  // dead row -> 0
        if (lane == 0) { g_blank[o] = 0.0f; g_lab[o] = 0.0f; }
        return;
    }

    const float4* p = reinterpret_cast<const float4*>(logits) + (size_t)gw * (Vv / 4);
    float4 a  = __ldcs(p + lane);
    float4 b4 = __ldcs(p + lane + 32);
    float4 c  = __ldcs(p + lane + 64);
    float4 dd = __ldcs(p + lane + 96);

    float s0 = (exp_fast(a.x)  + exp_fast(a.y))  + (exp_fast(a.z)  + exp_fast(a.w));
    float s1 = (exp_fast(b4.x) + exp_fast(b4.y)) + (exp_fast(b4.z) + exp_fast(b4.w));
    float s2 = (exp_fast(c.x)  + exp_fast(c.y))  + (exp_fast(c.z)  + exp_fast(c.w));
    float s3 = (exp_fast(dd.x) + exp_fast(dd.y)) + (exp_fast(dd.z) + exp_fast(dd.w));
    float s  = (s0 + s1) + (s2 + s3);
#pragma unroll
    for (int o2 = 16; o2; o2 >>= 1) s += __shfl_xor_sync(0xffffffffu, s, o2);

    float blank_logit = __shfl_sync(0xffffffffu, dd.w, 31);  // element 511

    if (lane == 0) {
        float rs = __fdividef(512.0f, s);     // 2^SC / sum  (MUFU rcp path)
        int tgt = targets[b * Uu + min(u, Uu - 1)];
        float lab_logit = __ldg(logits + (size_t)gw * Vv + tgt);
        g_blank[o] = exp_fast(blank_logit) * rs;   // pb * 2^SC
        g_lab[o]   = exp_fast(lab_logit)   * rs;   // pl * 2^SC
    }
}

// ---------------------------------------------------------------------------
// Kernel 2: MITM DP in LINEAR domain, one 128-thread block per batch.
// Launched with PDL: blocks come resident during lse, do setup, then HW-wait
// on grid dependency; 4 warps preload via cp.async, warps 0/1 compute:
//   warp0: forward alpha to cut dm (1 MUL + 1 FMA per cell per diagonal)
//   warp1: backward beta to dm
// Renorm every RNORM diagonals: warp-max -> scale by 2^(127-e), accumulate k.
// Combine: ll = lg2(sum_u A'[u]B'[u]) - SC*(dtar+1) + KF + KB   (log2 domain).
// ---------------------------------------------------------------------------
__global__ void __launch_bounds__(128) dp_kernel(const int* __restrict__ tl_arr,
                                                 const int* __restrict__ ul_arr,
                                                 float* __restrict__ out) {
    extern __shared__ float sm[];
    float* s_bl  = sm;
    float* s_la  = sm + NDIAG * DSTR;
    float* s_alp = sm + 2 * NDIAG * DSTR;        // 88: alpha' at the cut
    float* s_bet = s_alp + 88;                   // 88: beta'  at the cut
    int*   s_ki  = reinterpret_cast<int*>(s_bet + 88);  // [KF, KB]
    int b = blockIdx.x;

    // Inputs tl/ul are kernel inputs (not produced by lse): read pre-sync.
    int tl = __ldg(tl_arr + b), ul = __ldg(ul_arr + b);
    int dtar = tl - 1 + ul;
    int dm   = dtar >> 1;
    int n4   = (dtar + 1) * (DSTR / 4);
    const float4* gb = reinterpret_cast<const float4*>(g_blank + b * NDIAG * DSTR);
    const float4* gl = reinterpret_cast<const float4*>(g_lab   + b * NDIAG * DSTR);
    unsigned int sb = (unsigned int)__cvta_generic_to_shared(s_bl);
    unsigned int sl = (unsigned int)__cvta_generic_to_shared(s_la);

    // Wait for lse grid completion (HW dependency; no polling).
    cudaGridDependencySynchronize();

    // Async preload rows [0, dtar] of both tables (all 4 warps).
    for (int i = threadIdx.x; i < n4; i += 128) {
        cp16(sb + 16u * i, gb + i);
        cp16(sl + 16u * i, gl + i);
    }
    asm volatile("cp.async.commit_group;");
    asm volatile("cp.async.wait_group 0;");
    __syncthreads();

    int wid  = threadIdx.x >> 5;
    if (wid >= 2) return;                        // preload-only warps exit
    int lane = threadIdx.x & 31;
    int u0   = lane * 4;
    int uoff = min(u0, 84);
    // renorm mask: cells beyond ul excluded from the max (values >= 0 always)
    bool m0 = (u0     <= ul), m1 = (u0 + 1 <= ul),
         m2 = (u0 + 2 <= ul), m3 = (u0 + 3 <= ul);

    if (wid == 0) {
        // =================== FORWARD alpha': diag 1 .. dm ====================
        float v0 = (lane == 0) ? 1.0f : 0.0f, v1 = 0.0f, v2 = 0.0f, v3 = 0.0f;
        int K = 0, cd = RNORM;
        float4 cbl = *reinterpret_cast<const float4*>(s_bl + uoff);  // row 0
        float4 cla = *reinterpret_cast<const float4*>(s_la + uoff);
        for (int d = 1; d <= dm; ++d) {
            float4 nbl = *reinterpret_cast<const float4*>(s_bl + d * DSTR + uoff);
            float4 nla = *reinterpret_cast<const float4*>(s_la + d * DSTR + uoff);
            float vleft = __shfl_up_sync(0xffffffffu, v3,    1);
            float lleft = __shfl_up_sync(0xffffffffu, cla.w, 1);
            if (lane == 0) vleft = 0.0f;         // cell 0 has no left neighbor
            float nv0 = fmaf(v0, cbl.x, vleft * lleft);
            float nv1 = fmaf(v1, cbl.y, v0 * cla.x);
            float nv2 = fmaf(v2, cbl.z, v1 * cla.y);
            float nv3 = fmaf(v3, cbl.w, v2 * cla.z);
            v0 = nv0; v1 = nv1; v2 = nv2; v3 = nv3;
            cbl = nbl; cla = nla;
            if (--cd == 0) {                     // renormalize
                cd = RNORM;
                float mx = fmaxf(fmaxf(m0 ? v0 : 0.0f, m1 ? v1 : 0.0f),
                                 fmaxf(m2 ? v2 : 0.0f, m3 ? v3 : 0.0f));
                mx = warp_max(mx);
                int e = (__float_as_int(mx) >> 23) & 0xFF;
                e = max(e, 1);
                float sc = __int_as_float((254 - e) << 23);  // 2^(127-e)
                v0 *= sc; v1 *= sc; v2 *= sc; v3 *= sc;
                K += e - 127;
            }
        }
        {   // final renorm (bound values before the cross-warp product)
            float mx = fmaxf(fmaxf(m0 ? v0 : 0.0f, m1 ? v1 : 0.0f),
                             fmaxf(m2 ? v2 : 0.0f, m3 ? v3 : 0.0f));
            mx = warp_max(mx);
            int e = (__float_as_int(mx) >> 23) & 0xFF;
            e = max(e, 1);
            float sc = __int_as_float((254 - e) << 23);
            v0 *= sc; v1 *= sc; v2 *= sc; v3 *= sc;
            K += e - 127;
        }
        *reinterpret_cast<float4*>(s_alp + uoff) = make_float4(v0, v1, v2, v3);
        if (lane == 0) s_ki[0] = K;
    } else {
        // =================== BACKWARD beta': diag dtar-1 .. dm ===============
        float corner = s_bl[dtar * DSTR + ul];   // beta[tl-1][ul] = pb' there
        float w0 = (u0     == ul) ? corner : 0.0f;
        float w1 = (u0 + 1 == ul) ? corner : 0.0f;
        float w2 = (u0 + 2 == ul) ? corner : 0.0f;
        float w3 = (u0 + 3 == ul) ? corner : 0.0f;
        float wr = __shfl_down_sync(0xffffffffu, w0, 1);   // cell u0+4, cur diag
        int K = 0, cd = RNORM;
        float4 cbl, cla;
        if (dtar > dm) {
            cbl = *reinterpret_cast<const float4*>(s_bl + (dtar - 1) * DSTR + uoff);
            cla = *reinterpret_cast<const float4*>(s_la + (dtar - 1) * DSTR + uoff);
        }
        for (int d = dtar - 1; d >= dm; --d) {
            int dn = max(d - 1, 0);
            float4 nbl = *reinterpret_cast<const float4*>(s_bl + dn * DSTR + uoff);
            float4 nla = *reinterpret_cast<const float4*>(s_la + dn * DSTR + uoff);
            float nb0 = fmaf(w0, cbl.x, w1 * cla.x);
            float nwr = __shfl_down_sync(0xffffffffu, nb0, 1);
            float nb1 = fmaf(w1, cbl.y, w2 * cla.y);
            float nb2 = fmaf(w2, cbl.z, w3 * cla.z);
            float nb3 = fmaf(w3, cbl.w, wr * cla.w);  // cell 87: cla.w = 0 pad
            w0 = nb0; w1 = nb1; w2 = nb2; w3 = nb3; wr = nwr;
            cbl = nbl; cla = nla;
            if (--cd == 0) {                     // renormalize (all cells valid-or-0)
                cd = RNORM;
                float mx = warp_max(fmaxf(fmaxf(w0, w1), fmaxf(w2, w3)));
                int e = (__float_as_int(mx) >> 23) & 0xFF;
                e = max(e, 1);
                float sc = __int_as_float((254 - e) << 23);
                w0 *= sc; w1 *= sc; w2 *= sc; w3 *= sc;
                wr *= sc;                        // neighbor carries same scale
                K += e - 127;
            }
        }
        {   // final renorm
            float mx = warp_max(fmaxf(fmaxf(w0, w1), fmaxf(w2, w3)));
            int e = (__float_as_int(mx) >> 23) & 0xFF;
            e = max(e, 1);
            float sc = __int_as_float((254 - e) << 23);
            w0 *= sc; w1 *= sc; w2 *= sc; w3 *= sc;
            K += e - 127;
        }
        *reinterpret_cast<float4*>(s_bet + uoff) = make_float4(w0, w1, w2, w3);
        if (lane == 0) s_ki[1] = K;
    }

    asm volatile("bar.sync 1, 64;" ::: "memory");
    if (wid != 0) return;

    // ---------------- Combine at the cut: masked dot product ----------------
    int lo = max(0, dm - (tl - 1));
    int hi = min(dm, ul);
    float S = 0.0f;
    {
        int u = lane;
        if (u >= lo && u <= hi) S += s_alp[u] * s_bet[u];
        u = lane + 32;
        if (u >= lo && u <= hi) S += s_alp[u] * s_bet[u];
        u = lane + 64;
        if (u < 88 && u >= lo && u <= hi) S += s_alp[u] * s_bet[u];
    }
    S = warp_sum(S);

    if (lane == 0) {
        float l;  asm("lg2.approx.f32 %0, %1;" : "=f"(l) : "f"(S));
        g_ll[b] = l - (float)(SC * (dtar + 1)) + (float)(s_ki[0] + s_ki[1]);
        __threadfence();
        int prev = atomicAdd(&g_done, 1);
        if (prev == Bb - 1) {                     // deterministic final reduce
            __threadfence();
            float sll = 0.0f;
#pragma unroll
            for (int i = 0; i < Bb; ++i) sll += __ldcg(&g_ll[i]);
            out[0] = sll * (-LN2 / (float)Bb);
            g_done = 0;                           // reset for next graph replay
        }
    }
}

extern "C" void kernel_launch(void* const* d_in, const int* in_sizes, int n_in,
                              void* d_out, int out_size) {
    const float* logits  = (const float*)d_in[0];
    const int*   targets = (const int*)d_in[1];
    const int*   tl      = (const int*)d_in[2];
    const int*   ul      = (const int*)d_in[3];

    const int ROWS = Bb * Tt * U1;                 // 207360 rows, 8 warps/block
    lse_kernel<<<PADB + ROWS / 8, 256>>>(logits, targets, tl, ul);

    size_t smem = (2 * NDIAG * DSTR + 256) * sizeof(float);  // tables + buffers
    cudaFuncSetAttribute(dp_kernel, cudaFuncAttributeMaxDynamicSharedMemorySize, (int)smem);

    // PDL: dp blocks launch while lse runs; HW grid-dependency gates the reads.
    cudaLaunchConfig_t cfg = {};
    cfg.gridDim  = dim3(Bb);
    cfg.blockDim = dim3(128);
    cfg.dynamicSmemBytes = smem;
    cfg.stream = 0;
    cudaLaunchAttribute attrs[1];
    attrs[0].id = cudaLaunchAttributeProgrammaticStreamSerialization;
    attrs[0].val.programmaticStreamSerializationAllowed = 1;
    cfg.attrs = attrs;
    cfg.numAttrs = 1;
    cudaLaunchKernelEx(&cfg, dp_kernel, tl, ul, (float*)d_out);
}